// round 1
// baseline (speedup 1.0000x reference)
#include <cuda_runtime.h>
#include <cstdint>

#define Hh 200
#define Ww 196
#define Cc 256
#define NCAMS 6
#define SSZ 400
#define NCELLS (SSZ*SSZ)
#define NPTS (Hh*Ww)   // 39200
#define HQ (Hh/4)      // 50

__device__ float g_sum[NCELLS];
__device__ float g_cnt[NCELLS];
__device__ int   g_mask_mode;  // 0 = int32, 1 = uint8/bool, 2 = float32

// Fingerprint the mask buffer's dtype from its byte pattern.
// mask is ~90% true; over the first 400 bytes:
//   int32 0/1:  bytes at i%4==0 sometimes 1, bytes at i%4!=0 always 0
//   f32 0.0/1.0: bytes at i%4==0 always 0 (low byte), bytes at i%4!=0 sometimes nonzero
//   u8 bool:    both classes frequently nonzero
__global__ void probe_mask_kernel(const unsigned char* __restrict__ m) {
    int p0 = 0, p123 = 0;
    for (int i = 0; i < 400; ++i) {
        if (m[i]) { if ((i & 3) == 0) p0 = 1; else p123 = 1; }
    }
    int mode;
    if (p0 && p123)      mode = 1;   // u8 bool
    else if (p0)         mode = 0;   // int32
    else                 mode = 2;   // float32
    g_mask_mode = mode;
}

__global__ void zero_kernel() {
    int i = blockIdx.x * blockDim.x + threadIdx.x;
    if (i < NCELLS) { g_sum[i] = 0.f; g_cnt[i] = 0.f; }
}

// One thread per (cam, w, h-quad). Streams td_feats exactly once (coalesced
// float4 over innermost h), reduces over channels against s_w, then scatters
// a scalar + count per point.
__global__ __launch_bounds__(256) void fused_dot_scatter_kernel(
    const float* __restrict__ td, const float* __restrict__ cam,
    const float* __restrict__ lc, const void*  __restrict__ mask,
    const float* __restrict__ wcls)
{
    __shared__ float s_w[Cc];
    for (int i = threadIdx.x; i < Cc; i += blockDim.x) s_w[i] = wcls[i];
    __syncthreads();

    int tid = blockIdx.x * blockDim.x + threadIdx.x;
    if (tid >= NCAMS * Ww * HQ) return;
    int c   = tid / (Ww * HQ);
    int rem = tid % (Ww * HQ);
    int w   = rem / HQ;
    int hq  = rem % HQ;
    int h0  = hq * 4;

    // td flat index: ((c*C + ch)*W + w)*H + h ; h innermost, 16B aligned (H%4==0)
    const float4* __restrict__ base =
        (const float4*)(td + ((size_t)(c * Cc) * Ww + w) * Hh + h0);
    const int ch_stride4 = (Ww * Hh) / 4;  // 9800 float4 between channels

    float acc0 = 0.f, acc1 = 0.f, acc2 = 0.f, acc3 = 0.f;
    #pragma unroll 8
    for (int ch = 0; ch < Cc; ++ch) {
        float4 v = __ldg(base + ch * ch_stride4);
        float wv = s_w[ch];
        acc0 = fmaf(v.x, wv, acc0);
        acc1 = fmaf(v.y, wv, acc1);
        acc2 = fmaf(v.z, wv, acc2);
        acc3 = fmaf(v.w, wv, acc3);
    }

    const float* M = cam + c * 16;
    float m00 = M[0], m01 = M[1], m03 = M[3];
    float m10 = M[4], m11 = M[5], m13 = M[7];
    int mode = g_mask_mode;

    float accs[4] = {acc0, acc1, acc2, acc3};
    #pragma unroll
    for (int k = 0; k < 4; ++k) {
        int h = h0 + k;
        int n = h * Ww + w;                 // ravel order of (H, W)
        float x = lc[n];                    // row 0 of logits_coordinates
        float y = lc[NPTS + n];             // row 1
        bool mv;
        if (mode == 1)      mv = ((const unsigned char*)mask)[n] != 0;
        else if (mode == 0) mv = ((const int*)mask)[n] != 0;
        else                mv = ((const float*)mask)[n] != 0.f;

        float c0 = fmaf(m00, x, fmaf(m01, y, m03));
        float c1 = fmaf(m10, x, fmaf(m11, y, m13));
        // (coord + 100)/0.5 == (coord + 100)*2 exactly; jnp.round = half-to-even = rintf
        int i0 = (int)rintf((c0 + 100.0f) * 2.0f);
        int i1 = (int)rintf((c1 + 100.0f) * 2.0f);
        if (mv && i0 >= 0 && i0 < SSZ && i1 >= 0 && i1 < SSZ) {
            int cell = i0 * SSZ + i1;
            atomicAdd(&g_sum[cell], accs[k]);
            atomicAdd(&g_cnt[cell], 1.0f);
        }
    }
}

__global__ void final_kernel(float* __restrict__ out, const float* __restrict__ bcls) {
    int i = blockIdx.x * blockDim.x + threadIdx.x;
    if (i < NCELLS) {
        float cnt = g_cnt[i];
        // cnt==0 -> sum==0 -> 0/1 + b == b, matching jnp.where path
        out[i] = g_sum[i] / fmaxf(cnt, 1.0f) + bcls[0];
    }
}

extern "C" void kernel_launch(void* const* d_in, const int* in_sizes, int n_in,
                              void* d_out, int out_size) {
    const float* td   = (const float*)d_in[0];  // (1,6,256,196,200) f32
    const float* cam  = (const float*)d_in[1];  // (1,6,4,4) f32
    const float* lc   = (const float*)d_in[2];  // (4,39200) f32
    const void*  mask = (const void*) d_in[3];  // (200,196) bool-ish
    const float* wcls = (const float*)d_in[4];  // (256,) f32
    const float* bcls = (const float*)d_in[5];  // () f32
    float* out = (float*)d_out;                 // (1,1,400,400) f32

    probe_mask_kernel<<<1, 1>>>((const unsigned char*)mask);
    zero_kernel<<<(NCELLS + 255) / 256, 256>>>();

    int nthreads = NCAMS * Ww * HQ;             // 58800
    fused_dot_scatter_kernel<<<(nthreads + 255) / 256, 256>>>(td, cam, lc, mask, wcls);

    final_kernel<<<(NCELLS + 255) / 256, 256>>>(out, bcls);
}

// round 2
// speedup vs baseline: 1.0896x; 1.0896x over previous
#include <cuda_runtime.h>
#include <cstdint>

#define Hh 200
#define Ww 196
#define Cc 256
#define NCAMS 6
#define SSZ 400
#define NCELLS (SSZ*SSZ)
#define NPTS (Hh*Ww)     // 39200
#define HQ (Hh/4)        // 50
#define NSEG 4           // channel groups
#define CPG (Cc/NSEG)    // 64 channels per group

__device__ float g_sum[NCELLS];
__device__ float g_cnt[NCELLS];
__device__ int   g_mask_mode;   // 0 = int32, 1 = uint8/bool, 2 = float32

// Zero the accumulator grids (float4) and, in warp 0 of block 0, fingerprint
// the mask dtype in parallel:
//   view first 400 bytes as 100 u32 words.
//   int32 0/1  : low byte sometimes set, high-3 bytes never
//   f32 0/1.0f : low byte never set, high bytes sometimes (0x3f800000)
//   u8 bool    : both (mask ~90% true)
__global__ __launch_bounds__(256) void zero_probe_kernel(const unsigned char* __restrict__ m) {
    int i = blockIdx.x * blockDim.x + threadIdx.x;
    if (i < NCELLS / 4) {
        ((float4*)g_sum)[i] = make_float4(0.f, 0.f, 0.f, 0.f);
        ((float4*)g_cnt)[i] = make_float4(0.f, 0.f, 0.f, 0.f);
    }
    if (blockIdx.x == 0 && threadIdx.x < 32) {
        const unsigned* mw = (const unsigned*)m;
        unsigned lo = 0, hi = 0;
        #pragma unroll
        for (int k = 0; k < 4; ++k) {
            unsigned v = mw[threadIdx.x + 32 * k + ((threadIdx.x + 32 * k < 100) ? 0 : -32)];
            // clamp: words 100..127 -> re-read earlier words (harmless, same class)
            lo |= (v & 0xFFu);
            hi |= (v & 0xFFFFFF00u);
        }
        unsigned any_lo = __ballot_sync(0xFFFFFFFF, lo != 0);
        unsigned any_hi = __ballot_sync(0xFFFFFFFF, hi != 0);
        if (threadIdx.x == 0) {
            int mode;
            if (any_lo && any_hi) mode = 1;       // u8 bool
            else if (any_lo)      mode = 0;       // int32
            else                  mode = 2;       // float32
            g_mask_mode = mode;
        }
    }
}

// One thread per (cam, w, chan-group, h-quad). Streams td_feats exactly once
// (coalesced float4 over innermost h), partial-dots 64 channels against s_w,
// then scatters the partial scalar per point (group 0 also bumps the count).
__global__ __launch_bounds__(256) void fused_dot_scatter_kernel(
    const float* __restrict__ td, const float* __restrict__ cam,
    const float* __restrict__ lc, const void*  __restrict__ mask,
    const float* __restrict__ wcls)
{
    __shared__ float s_w[Cc];
    for (int i = threadIdx.x; i < Cc; i += blockDim.x) s_w[i] = wcls[i];
    __syncthreads();

    int tid = blockIdx.x * blockDim.x + threadIdx.x;
    if (tid >= NCAMS * Ww * NSEG * HQ) return;
    // hq innermost for coalescing, then chan-group, then w, then cam
    int hq  = tid % HQ;
    int t2  = tid / HQ;
    int seg = t2 % NSEG;
    int t3  = t2 / NSEG;
    int w   = t3 % Ww;
    int c   = t3 / Ww;
    int h0  = hq * 4;
    int ch0 = seg * CPG;

    // td flat index: ((c*C + ch)*W + w)*H + h ; h innermost, 16B aligned (H%4==0)
    const float4* __restrict__ base =
        (const float4*)(td + ((size_t)(c * Cc + ch0) * Ww + w) * Hh + h0);
    const int ch_stride4 = (Ww * Hh) / 4;   // 9800 float4 between channels

    float acc0 = 0.f, acc1 = 0.f, acc2 = 0.f, acc3 = 0.f;
    #pragma unroll 8
    for (int ch = 0; ch < CPG; ++ch) {
        float4 v = __ldg(base + ch * ch_stride4);
        float wv = s_w[ch0 + ch];
        acc0 = fmaf(v.x, wv, acc0);
        acc1 = fmaf(v.y, wv, acc1);
        acc2 = fmaf(v.z, wv, acc2);
        acc3 = fmaf(v.w, wv, acc3);
    }

    const float* M = cam + c * 16;
    float m00 = M[0], m01 = M[1], m03 = M[3];
    float m10 = M[4], m11 = M[5], m13 = M[7];
    int mode = g_mask_mode;

    float accs[4] = {acc0, acc1, acc2, acc3};
    #pragma unroll
    for (int k = 0; k < 4; ++k) {
        int h = h0 + k;
        int n = h * Ww + w;               // ravel order of (H, W)
        float x = lc[n];                  // row 0 of logits_coordinates
        float y = lc[NPTS + n];           // row 1
        bool mv;
        if (mode == 1)      mv = ((const unsigned char*)mask)[n] != 0;
        else if (mode == 0) mv = ((const int*)mask)[n] != 0;
        else                mv = ((const float*)mask)[n] != 0.f;

        float c0 = fmaf(m00, x, fmaf(m01, y, m03));
        float c1 = fmaf(m10, x, fmaf(m11, y, m13));
        // (coord + 100)/0.5 == (coord + 100)*2 exactly; jnp.round = half-even = rintf
        int i0 = (int)rintf((c0 + 100.0f) * 2.0f);
        int i1 = (int)rintf((c1 + 100.0f) * 2.0f);
        if (mv && i0 >= 0 && i0 < SSZ && i1 >= 0 && i1 < SSZ) {
            int cell = i0 * SSZ + i1;
            atomicAdd(&g_sum[cell], accs[k]);     // partial dot; linear so OK
            if (seg == 0) atomicAdd(&g_cnt[cell], 1.0f);
        }
    }
}

__global__ __launch_bounds__(256) void final_kernel(float* __restrict__ out,
                                                    const float* __restrict__ bcls) {
    int i = blockIdx.x * blockDim.x + threadIdx.x;
    if (i >= NCELLS / 4) return;
    float  b = __ldg(bcls);
    float4 s = ((const float4*)g_sum)[i];
    float4 n = ((const float4*)g_cnt)[i];
    float4 o;
    o.x = s.x / fmaxf(n.x, 1.0f) + b;
    o.y = s.y / fmaxf(n.y, 1.0f) + b;
    o.z = s.z / fmaxf(n.z, 1.0f) + b;
    o.w = s.w / fmaxf(n.w, 1.0f) + b;
    ((float4*)out)[i] = o;
}

extern "C" void kernel_launch(void* const* d_in, const int* in_sizes, int n_in,
                              void* d_out, int out_size) {
    const float* td   = (const float*)d_in[0];  // (1,6,256,196,200) f32
    const float* cam  = (const float*)d_in[1];  // (1,6,4,4) f32
    const float* lc   = (const float*)d_in[2];  // (4,39200) f32
    const void*  mask = (const void*) d_in[3];  // (200,196) bool-ish
    const float* wcls = (const float*)d_in[4];  // (256,) f32
    const float* bcls = (const float*)d_in[5];  // () f32
    float* out = (float*)d_out;                 // (1,1,400,400) f32

    zero_probe_kernel<<<(NCELLS / 4 + 255) / 256, 256>>>((const unsigned char*)mask);

    int nthreads = NCAMS * Ww * NSEG * HQ;      // 235200
    fused_dot_scatter_kernel<<<(nthreads + 255) / 256, 256>>>(td, cam, lc, mask, wcls);

    final_kernel<<<(NCELLS / 4 + 255) / 256, 256>>>(out, bcls);
}

// round 3
// speedup vs baseline: 1.1214x; 1.0292x over previous
#include <cuda_runtime.h>
#include <cstdint>

#define Hh 200
#define Ww 196
#define Cc 256
#define NCAMS 6
#define SSZ 400
#define NCELLS (SSZ*SSZ)
#define NPTS (Hh*Ww)     // 39200
#define HQ (Hh/4)        // 50
#define NSEG 4           // channel groups
#define CPG (Cc/NSEG)    // 64 channels per group

// Zero-initialized at module load; final_kernel restores them to zero every
// launch, so every kernel_launch call sees zeroed scratch (deterministic).
__device__ float g_sum[NCELLS];
__device__ float g_cnt[NCELLS];

// One thread per (cam, w, chan-group, h-quad). Streams td_feats exactly once
// (coalesced float4 over innermost h), partial-dots 64 channels against s_w,
// then scatters the partial scalar per point (group 0 also bumps the count).
// Warp 0 fingerprints the mask dtype from its byte pattern (mask ~90% true):
//   int32 0/1  : low byte of words sometimes set, upper 3 bytes never
//   f32 0/1.0f : low byte never set, upper bytes sometimes (0x3f800000)
//   u8 bool    : both populated
__global__ __launch_bounds__(256) void fused_dot_scatter_kernel(
    const float* __restrict__ td, const float* __restrict__ cam,
    const float* __restrict__ lc, const void*  __restrict__ mask,
    const float* __restrict__ wcls)
{
    __shared__ float s_w[Cc];
    __shared__ int   s_mode;

    if (threadIdx.x < 32) {
        const unsigned* mw = (const unsigned*)mask;
        unsigned lo = 0, hi = 0;
        #pragma unroll
        for (int k = 0; k < 3; ++k) {           // words 0..95 (384 B of mask)
            unsigned v = mw[threadIdx.x + 32 * k];
            lo |= (v & 0xFFu);
            hi |= (v & 0xFFFFFF00u);
        }
        unsigned any_lo = __ballot_sync(0xFFFFFFFF, lo != 0);
        unsigned any_hi = __ballot_sync(0xFFFFFFFF, hi != 0);
        if (threadIdx.x == 0) {
            int mode;
            if (any_lo && any_hi) mode = 1;     // u8 bool
            else if (any_lo)      mode = 0;     // int32
            else                  mode = 2;     // float32
            s_mode = mode;
        }
    }
    for (int i = threadIdx.x; i < Cc; i += blockDim.x) s_w[i] = wcls[i];
    __syncthreads();

    int tid = blockIdx.x * blockDim.x + threadIdx.x;
    if (tid >= NCAMS * Ww * NSEG * HQ) return;
    // hq innermost for coalescing, then chan-group, then w, then cam
    int hq  = tid % HQ;
    int t2  = tid / HQ;
    int seg = t2 % NSEG;
    int t3  = t2 / NSEG;
    int w   = t3 % Ww;
    int c   = t3 / Ww;
    int h0  = hq * 4;
    int ch0 = seg * CPG;

    // td flat index: ((c*C + ch)*W + w)*H + h ; h innermost, 16B aligned (H%4==0)
    const float4* __restrict__ base =
        (const float4*)(td + ((size_t)(c * Cc + ch0) * Ww + w) * Hh + h0);
    const int ch_stride4 = (Ww * Hh) / 4;   // 9800 float4 between channels

    float acc0 = 0.f, acc1 = 0.f, acc2 = 0.f, acc3 = 0.f;
    #pragma unroll 8
    for (int ch = 0; ch < CPG; ++ch) {
        float4 v = __ldg(base + ch * ch_stride4);
        float wv = s_w[ch0 + ch];
        acc0 = fmaf(v.x, wv, acc0);
        acc1 = fmaf(v.y, wv, acc1);
        acc2 = fmaf(v.z, wv, acc2);
        acc3 = fmaf(v.w, wv, acc3);
    }

    const float* M = cam + c * 16;
    float m00 = M[0], m01 = M[1], m03 = M[3];
    float m10 = M[4], m11 = M[5], m13 = M[7];
    int mode = s_mode;

    float accs[4] = {acc0, acc1, acc2, acc3};
    #pragma unroll
    for (int k = 0; k < 4; ++k) {
        int h = h0 + k;
        int n = h * Ww + w;               // ravel order of (H, W)
        float x = lc[n];                  // row 0 of logits_coordinates
        float y = lc[NPTS + n];           // row 1
        bool mv;
        if (mode == 1)      mv = ((const unsigned char*)mask)[n] != 0;
        else if (mode == 0) mv = ((const int*)mask)[n] != 0;
        else                mv = ((const float*)mask)[n] != 0.f;

        float c0 = fmaf(m00, x, fmaf(m01, y, m03));
        float c1 = fmaf(m10, x, fmaf(m11, y, m13));
        // (coord + 100)/0.5 == (coord + 100)*2 exactly; jnp.round = half-even = rintf
        int i0 = (int)rintf((c0 + 100.0f) * 2.0f);
        int i1 = (int)rintf((c1 + 100.0f) * 2.0f);
        if (mv && i0 >= 0 && i0 < SSZ && i1 >= 0 && i1 < SSZ) {
            int cell = i0 * SSZ + i1;
            atomicAdd(&g_sum[cell], accs[k]);     // partial dot; linear so OK
            if (seg == 0) atomicAdd(&g_cnt[cell], 1.0f);
        }
    }
}

// Consumes the accumulators AND resets them to zero for the next launch,
// removing the need for a separate zeroing kernel.
__global__ __launch_bounds__(256) void final_kernel(float* __restrict__ out,
                                                    const float* __restrict__ bcls) {
    int i = blockIdx.x * blockDim.x + threadIdx.x;
    if (i >= NCELLS / 4) return;
    float  b = __ldg(bcls);
    float4 s = ((const float4*)g_sum)[i];
    float4 n = ((const float4*)g_cnt)[i];
    float4 o;
    o.x = s.x / fmaxf(n.x, 1.0f) + b;
    o.y = s.y / fmaxf(n.y, 1.0f) + b;
    o.z = s.z / fmaxf(n.z, 1.0f) + b;
    o.w = s.w / fmaxf(n.w, 1.0f) + b;
    ((float4*)out)[i] = o;
    float4 z = make_float4(0.f, 0.f, 0.f, 0.f);
    ((float4*)g_sum)[i] = z;
    ((float4*)g_cnt)[i] = z;
}

extern "C" void kernel_launch(void* const* d_in, const int* in_sizes, int n_in,
                              void* d_out, int out_size) {
    const float* td   = (const float*)d_in[0];  // (1,6,256,196,200) f32
    const float* cam  = (const float*)d_in[1];  // (1,6,4,4) f32
    const float* lc   = (const float*)d_in[2];  // (4,39200) f32
    const void*  mask = (const void*) d_in[3];  // (200,196) bool-ish
    const float* wcls = (const float*)d_in[4];  // (256,) f32
    const float* bcls = (const float*)d_in[5];  // () f32
    float* out = (float*)d_out;                 // (1,1,400,400) f32

    int nthreads = NCAMS * Ww * NSEG * HQ;      // 235200
    fused_dot_scatter_kernel<<<(nthreads + 255) / 256, 256>>>(td, cam, lc, mask, wcls);

    final_kernel<<<(NCELLS / 4 + 255) / 256, 256>>>(out, bcls);
}